// round 16
// baseline (speedup 1.0000x reference)
#include <cuda_runtime.h>
#include <cuda_fp16.h>
#include <cstdint>

#define NN 20000
#define NE 320000
#define DD 256
#define LGC 4
#define KCH 768
#define KCL 1024
#define BN_EPS 1e-5f

// ==================== scratch ====================
__device__ float g_deg[NN];
__device__ float g_norm[NE];
__device__ int   g_cnt[NN];
__device__ int   g_cur[NN];
__device__ int   g_ptr[NN + 1];
__device__ int   g_eid[NE];
__device__ int   g_src[NE];
__device__ float g_w[NE];
__device__ float g_t1[(size_t)NN * DD];        // T1 fp32 (prop phase-1 gather input)
__device__ float g_jk[(size_t)NN * 1024];      // JK fp32 (next-layer T0 gather input)
// packed fp16 hi/lo A-operand copies: word w = half2 of cols (2w, 2w+1)
__device__ uint32_t g_fph[(size_t)NN * 128];
__device__ uint32_t g_fpl[(size_t)NN * 128];
__device__ uint32_t g_t1ph[(size_t)NN * 128];
__device__ uint32_t g_t1pl[(size_t)NN * 128];
__device__ uint32_t g_t2ph[(size_t)NN * 128];
__device__ uint32_t g_t2pl[(size_t)NN * 128];
__device__ uint32_t g_jkph[(size_t)NN * 512];
__device__ uint32_t g_jkpl[(size_t)NN * 512];
// transposed fp16 weights (single copy): [256 n][K/2 kpairs]
__device__ uint32_t g_wch[LGC * 256 * (KCH / 2)];
__device__ uint32_t g_wcl[256 * (KCL / 2)];

__device__ __forceinline__ uint32_t packh(__half a, __half b) {
    return (uint32_t)__half_as_ushort(a) | ((uint32_t)__half_as_ushort(b) << 16);
}

// split two fp32 into fp16 hi/lo half2 words (A = hi + lo captures ~22 mantissa bits)
__device__ __forceinline__ void split2(float x, float y, uint32_t& hi, uint32_t& lo) {
    __half h0 = __float2half_rn(x), h1 = __float2half_rn(y);
    float r0 = x - __half2float(h0), r1 = y - __half2float(h1);
    hi = packh(h0, h1);
    lo = packh(__float2half_rn(r0), __float2half_rn(r1));
}

__device__ __forceinline__ uint32_t smem_u32(const void* p) {
    uint32_t a;
    asm("{ .reg .u64 t; cvta.to.shared.u64 t, %1; cvt.u32.u64 %0, t; }" : "=r"(a) : "l"(p));
    return a;
}

__device__ __forceinline__ void ldm_x4(uint32_t r[4], uint32_t addr) {
    asm volatile("ldmatrix.sync.aligned.m8n8.x4.shared.b16 {%0,%1,%2,%3}, [%4];"
                 : "=r"(r[0]), "=r"(r[1]), "=r"(r[2]), "=r"(r[3]) : "r"(addr));
}

__device__ __forceinline__ void mma16816(float c[4], const uint32_t a[4], const uint32_t b0,
                                         const uint32_t b1) {
    asm volatile(
        "mma.sync.aligned.m16n8k16.row.col.f32.f16.f16.f32 "
        "{%0,%1,%2,%3}, {%4,%5,%6,%7}, {%8,%9}, {%0,%1,%2,%3};"
        : "+f"(c[0]), "+f"(c[1]), "+f"(c[2]), "+f"(c[3])
        : "r"(a[0]), "r"(a[1]), "r"(a[2]), "r"(a[3]), "r"(b0), "r"(b1));
}

__device__ __forceinline__ void cpa16(uint32_t dst, const void* src, int sz) {
    asm volatile("cp.async.cg.shared.global [%0], [%1], 16, %2;"
                 :: "r"(dst), "l"(src), "r"(sz));
}
#define CP_COMMIT() asm volatile("cp.async.commit_group;" ::: "memory")
#define CP_WAIT1()  asm volatile("cp.async.wait_group 1;" ::: "memory")
#define CP_WAIT0()  asm volatile("cp.async.wait_group 0;" ::: "memory")

// ==================== setup kernels ====================
// deg (weighted) + cnt (edge count per target) in one pass
__global__ void k_deg(const int* __restrict__ row, const int* __restrict__ col,
                      const float* __restrict__ ew) {
    int e = blockIdx.x * blockDim.x + threadIdx.x;
    if (e < NE) {
        atomicAdd(&g_deg[row[e]], ew[e]);
        atomicAdd(&g_cnt[col[e]], 1);
    }
}

__device__ __forceinline__ float dis_of(float d) {
    float y = 0.f;
    if (d > 0.f) {
        y = rsqrtf(d);
        y = y * (1.5f - 0.5f * d * y * y);  // Newton refine (matches prior k_dis numerics)
    }
    return y;
}

__global__ void k_norm(const int* __restrict__ row, const int* __restrict__ col,
                       const float* __restrict__ ew, float* __restrict__ out_ew) {
    int e = blockIdx.x * blockDim.x + threadIdx.x;
    if (e < NE) {
        float w = ew[e];
        float ir = dis_of(g_deg[row[e]]);
        float ic = dis_of(g_deg[col[e]]);
        g_norm[e] = -(ir * w * ic);
        out_ew[e] = w;
    }
}

__global__ void k_scan() {
    __shared__ int sh[1024];
    const int CH = 20;
    int tid = threadIdx.x;
    int base = tid * CH;
    int s = 0;
    for (int i = 0; i < CH; i++) {
        int idx = base + i;
        if (idx < NN) s += g_cnt[idx];
    }
    sh[tid] = s;
    __syncthreads();
    for (int off = 1; off < 1024; off <<= 1) {
        int v = (tid >= off) ? sh[tid - off] : 0;
        __syncthreads();
        sh[tid] += v;
        __syncthreads();
    }
    int run = (tid == 0) ? 0 : sh[tid - 1];
    for (int i = 0; i < CH; i++) {
        int idx = base + i;
        if (idx < NN) { g_ptr[idx] = run; run += g_cnt[idx]; }
    }
    if (tid == 1023) g_ptr[NN] = sh[1023];
}

__global__ void k_scatter(const int* __restrict__ col) {
    int e = blockIdx.x * blockDim.x + threadIdx.x;
    if (e < NE) {
        int c = col[e];
        int pos = g_ptr[c] + atomicAdd(&g_cur[c], 1);
        g_eid[pos] = e;
    }
}

__global__ void k_sortfill(const int* __restrict__ row) {
    int c = blockIdx.x * blockDim.x + threadIdx.x;
    if (c >= NN) return;
    int b = g_ptr[c], t = g_ptr[c + 1];
    for (int i = b + 1; i < t; i++) {
        int v = g_eid[i];
        int j = i - 1;
        while (j >= b && g_eid[j] > v) { g_eid[j + 1] = g_eid[j]; j--; }
        g_eid[j + 1] = v;
    }
    for (int p = b; p < t; p++) {
        int e = g_eid[p];
        g_src[p] = row[e];
        g_w[p] = g_norm[e];
    }
}

// ==================== fused prep: zero + feature split + weight fp16 packs ====================
#define PREP_FEAT_OFF  NN
#define PREP_CHEB_OFF  (NN + NN * 128)
#define PREP_W1_OFF    (PREP_CHEB_OFF + 4 * 98304)
#define PREP_TOTAL     (PREP_W1_OFF + 131072)

__global__ void k_prepall(const float* __restrict__ feat, const float* __restrict__ cheb_w,
                          const float* __restrict__ w1) {
    int idx = blockIdx.x * blockDim.x + threadIdx.x;
    if (idx < NN) {
        g_deg[idx] = 0.f; g_cnt[idx] = 0; g_cur[idx] = 0;
        return;
    }
    if (idx < PREP_CHEB_OFF) {
        int i = idx - PREP_FEAT_OFF;
        int n = i >> 7, w = i & 127;
        float2 v = *(const float2*)(feat + (size_t)n * 256 + 2 * w);
        uint32_t hi, lo;
        split2(v.x, v.y, hi, lo);
        g_fph[i] = hi;
        g_fpl[i] = lo;
        return;
    }
    if (idx < PREP_W1_OFF) {
        int i = idx - PREP_CHEB_OFF;
        int l = i / 98304, o = i % 98304;
        int n = o & 255, kp = o >> 8;             // kp in [0, 384)
        const float* B = cheb_w + (size_t)l * 3 * 256 * 256;
        uint32_t w = packh(__float2half_rn(B[(size_t)(2 * kp) * 256 + n]),
                           __float2half_rn(B[(size_t)(2 * kp + 1) * 256 + n]));
        g_wch[(size_t)l * 256 * (KCH / 2) + (size_t)n * (KCH / 2) + kp] = w;
        return;
    }
    if (idx < PREP_TOTAL) {
        int i = idx - PREP_W1_OFF;
        int n = i & 255, kp = i >> 8;             // kp in [0, 512)
        uint32_t w = packh(__float2half_rn(w1[(size_t)(2 * kp) * 256 + n]),
                           __float2half_rn(w1[(size_t)(2 * kp + 1) * 256 + n]));
        g_wcl[(size_t)n * (KCL / 2) + kp] = w;
    }
}

// ==================== cheb propagation (8-edge unroll) ====================
__global__ void k_prop(const float* __restrict__ feat, int l, int phase) {
    int c = blockIdx.x * 2 + threadIdx.y;
    if (c >= NN) return;
    int t = threadIdx.x;  // 0..63, float4 each
    const float* xin = (l == 0) ? feat : (g_jk + (size_t)(l - 1) * 256);
    int xstride = (l == 0) ? 256 : 1024;
    const float* xb;
    int xs;
    if (phase == 0) { xb = xin; xs = xstride; }
    else            { xb = g_t1; xs = 256; }

    float4 acc = make_float4(0.f, 0.f, 0.f, 0.f);
    int b = g_ptr[c], e = g_ptr[c + 1];
    int p = b;
    for (; p + 8 <= e; p += 8) {
        float w[8];
        const float* a[8];
#pragma unroll
        for (int i = 0; i < 8; i++) {
            w[i] = g_w[p + i];
            a[i] = xb + (size_t)g_src[p + i] * xs + 4 * t;
        }
        float4 v[8];
#pragma unroll
        for (int i = 0; i < 8; i++) v[i] = *(const float4*)a[i];
#pragma unroll
        for (int i = 0; i < 8; i++) {
            acc.x += w[i] * v[i].x;
            acc.y += w[i] * v[i].y;
            acc.z += w[i] * v[i].z;
            acc.w += w[i] * v[i].w;
        }
    }
    for (; p + 4 <= e; p += 4) {
        float w0 = g_w[p], w1 = g_w[p + 1], w2 = g_w[p + 2], w3 = g_w[p + 3];
        int s0 = g_src[p], s1 = g_src[p + 1], s2 = g_src[p + 2], s3 = g_src[p + 3];
        float4 v0 = *(const float4*)(xb + (size_t)s0 * xs + 4 * t);
        float4 v1 = *(const float4*)(xb + (size_t)s1 * xs + 4 * t);
        float4 v2 = *(const float4*)(xb + (size_t)s2 * xs + 4 * t);
        float4 v3 = *(const float4*)(xb + (size_t)s3 * xs + 4 * t);
        acc.x += w0 * v0.x + w1 * v1.x + w2 * v2.x + w3 * v3.x;
        acc.y += w0 * v0.y + w1 * v1.y + w2 * v2.y + w3 * v3.y;
        acc.z += w0 * v0.z + w1 * v1.z + w2 * v2.z + w3 * v3.z;
        acc.w += w0 * v0.w + w1 * v1.w + w2 * v2.w + w3 * v3.w;
    }
    for (; p < e; p++) {
        float w0 = g_w[p];
        int s0 = g_src[p];
        float4 v0 = *(const float4*)(xb + (size_t)s0 * xs + 4 * t);
        acc.x += w0 * v0.x; acc.y += w0 * v0.y;
        acc.z += w0 * v0.z; acc.w += w0 * v0.w;
    }
    uint32_t h0, l0, h1, l1;
    if (phase == 0) {
        *(float4*)(g_t1 + (size_t)c * 256 + 4 * t) = acc;
        split2(acc.x, acc.y, h0, l0);
        split2(acc.z, acc.w, h1, l1);
        size_t w = (size_t)c * 128 + 2 * t;
        g_t1ph[w] = h0; g_t1ph[w + 1] = h1;
        g_t1pl[w] = l0; g_t1pl[w + 1] = l1;
    } else {
        float4 v0 = *(const float4*)(xin + (size_t)c * xstride + 4 * t);
        acc.x = 2.f * acc.x - v0.x;
        acc.y = 2.f * acc.y - v0.y;
        acc.z = 2.f * acc.z - v0.z;
        acc.w = 2.f * acc.w - v0.w;
        split2(acc.x, acc.y, h0, l0);
        split2(acc.z, acc.w, h1, l1);
        size_t w = (size_t)c * 128 + 2 * t;
        g_t2ph[w] = h0; g_t2ph[w + 1] = h1;
        g_t2pl[w] = l0; g_t2pl[w + 1] = l1;
    }
}

// ==================== mma.sync fp16 GEMM (2-product), BM=64, 2 CTAs/SM ====================
// Grid (313), 256 threads = 8 warps (1 M x 8 N); warp tile 64x32; K-chunk 64.
// SMEM buffer (48KB x2): Ahi 8K | Alo 8K | B 32K, XOR-16B swizzled 128B rows.
// C = (Ah + Al) @ Bh.
#define BUFSZ 49152u
#define GSM_TOTAL (2 * 49152)

template <int EPI>
__global__ void __launch_bounds__(256, 2)
k_mmagemm(int l, const float* __restrict__ bias, const float* __restrict__ gamma,
          const float* __restrict__ beta, const float* __restrict__ mean,
          const float* __restrict__ var, const float* __restrict__ w2,
          const float* __restrict__ b2, float* __restrict__ out) {
    extern __shared__ char smem[];
    __shared__ float lpart[64][8][2];
    const int K = (EPI == 0) ? KCH : KCL;
    const int Khalf = K >> 1;
    const uint32_t* Bw = (EPI == 0) ? (g_wch + (size_t)l * 256 * (KCH / 2)) : g_wcl;
    const int jkoff = l * 256;

    uint32_t sm = smem_u32(smem);
    int tid = threadIdx.x;
    int wid = tid >> 5, lane = tid & 31;
    int wn = wid;                               // 8 warps across N
    int brow = blockIdx.x * 64;

    float acc[4][4][4];
#pragma unroll
    for (int i = 0; i < 4; i++)
#pragma unroll
        for (int j = 0; j < 4; j++)
#pragma unroll
            for (int q = 0; q < 4; q++) acc[i][j][q] = 0.f;

    int a_mi = lane >> 3;
    int a_row = ((a_mi & 1) << 3) + (lane & 7);
    int a_k8 = a_mi >> 1;                       // 16B-chunk offset 0/1
    int b_nrow = (((lane >> 4) & 1) << 3) + (lane & 7);
    int b_k8 = (lane >> 3) & 1;

    const int nchunks = K >> 6;

    auto stage = [&](int c) {
        uint32_t base = sm + (uint32_t)(c & 1) * BUFSZ;
        uint32_t aHi = base, aLo = base + 8192, bS = base + 16384;
        const uint32_t *Ah, *Al;
        int aws, cw;
        if (EPI == 0) {
            int seg = c >> 2, sc = (c & 3) * 32;
            if (seg == 0) {
                if (l == 0) { Ah = g_fph; Al = g_fpl; aws = 128; cw = sc; }
                else { Ah = g_jkph + (size_t)(l - 1) * 128; Al = g_jkpl + (size_t)(l - 1) * 128;
                       aws = 512; cw = sc; }
            } else if (seg == 1) { Ah = g_t1ph; Al = g_t1pl; aws = 128; cw = sc; }
            else                 { Ah = g_t2ph; Al = g_t2pl; aws = 128; cw = sc; }
        } else {
            Ah = g_jkph; Al = g_jkpl; aws = 512; cw = c * 32;
        }
        // A: 64 rows x 8 chunks, hi+lo -> 512 entries, 2/thread (2 cp each)
#pragma unroll
        for (int i = 0; i < 2; i++) {
            int idx = tid + i * 256;            // 0..511
            int r = idx >> 3, ch = idx & 7;
            int gr = brow + r;
            int ok = (gr < NN);
            size_t go = (size_t)(ok ? gr : 0) * aws + cw + ch * 4;
            uint32_t d = (uint32_t)(r * 128) + ((uint32_t)(ch ^ (r & 7)) << 4);
            cpa16(aHi + d, Ah + go, ok ? 16 : 0);
            cpa16(aLo + d, Al + go, ok ? 16 : 0);
        }
        // B: 256 rows x 8 chunks = 2048 -> 8/thread
#pragma unroll
        for (int i = 0; i < 8; i++) {
            int idx = tid + i * 256;            // 0..2047
            int n = idx >> 3, ch = idx & 7;
            size_t go = (size_t)n * Khalf + c * 32 + ch * 4;
            uint32_t d = (uint32_t)(n * 128) + ((uint32_t)(ch ^ (n & 7)) << 4);
            cpa16(bS + d, Bw + go, 16);
        }
        CP_COMMIT();
    };

    stage(0);
    for (int c = 0; c < nchunks; c++) {
        if (c + 1 < nchunks) { stage(c + 1); CP_WAIT1(); }
        else                 { CP_WAIT0(); }
        __syncthreads();

        uint32_t base = sm + (uint32_t)(c & 1) * BUFSZ;
        uint32_t aHi = base, aLo = base + 8192, bS = base + 16384;
#pragma unroll
        for (int kb = 0; kb < 4; kb++) {
            uint32_t bh[2][4];
#pragma unroll
            for (int np = 0; np < 2; np++) {
                int row = wn * 32 + np * 16 + b_nrow;
                uint32_t off = (uint32_t)(row * 128)
                             + ((uint32_t)((kb * 2 + b_k8) ^ (row & 7)) << 4);
                ldm_x4(bh[np], bS + off);
            }
#pragma unroll
            for (int mb = 0; mb < 4; mb++) {
                uint32_t ah[4], al[4];
                int row = mb * 16 + a_row;
                uint32_t off = (uint32_t)(row * 128)
                             + ((uint32_t)((kb * 2 + a_k8) ^ (row & 7)) << 4);
                ldm_x4(ah, aHi + off);
                ldm_x4(al, aLo + off);
#pragma unroll
                for (int nb = 0; nb < 4; nb++) {
                    int p = nb >> 1, q = (nb & 1) * 2;
                    mma16816(acc[mb][nb], ah, bh[p][q], bh[p][q + 1]);
                    mma16816(acc[mb][nb], al, bh[p][q], bh[p][q + 1]);
                }
            }
        }
        __syncthreads();
    }

    int gr_base = brow + (lane >> 2);
    int cg_base = wn * 32 + (lane & 3) * 2;
    if (EPI == 0) {
#pragma unroll
        for (int mb = 0; mb < 4; mb++) {
#pragma unroll
            for (int nb = 0; nb < 4; nb++) {
                int cg = cg_base + nb * 8;
                int r0 = gr_base + mb * 16;
                int r1 = r0 + 8;
                float* a = acc[mb][nb];
                if (r0 < NN) {
                    float vx = fmaxf(a[0], 0.f), vy = fmaxf(a[1], 0.f);
                    *(float2*)(g_jk + (size_t)r0 * 1024 + jkoff + cg) = make_float2(vx, vy);
                    uint32_t hi, lo;
                    split2(vx, vy, hi, lo);
                    size_t w = (size_t)r0 * 512 + ((jkoff + cg) >> 1);
                    g_jkph[w] = hi;
                    g_jkpl[w] = lo;
                }
                if (r1 < NN) {
                    float vx = fmaxf(a[2], 0.f), vy = fmaxf(a[3], 0.f);
                    *(float2*)(g_jk + (size_t)r1 * 1024 + jkoff + cg) = make_float2(vx, vy);
                    uint32_t hi, lo;
                    split2(vx, vy, hi, lo);
                    size_t w = (size_t)r1 * 512 + ((jkoff + cg) >> 1);
                    g_jkph[w] = hi;
                    g_jkpl[w] = lo;
                }
            }
        }
    } else {
#pragma unroll
        for (int mb = 0; mb < 4; mb++) {
            float p0a = 0.f, p0b = 0.f, p1a = 0.f, p1b = 0.f;
#pragma unroll
            for (int nb = 0; nb < 4; nb++) {
                int cg = cg_base + nb * 8;
                float* a = acc[mb][nb];
                float b0 = bias[cg], b1 = bias[cg + 1];
                float s0 = gamma[cg] * rsqrtf(var[cg] + BN_EPS);
                float s1 = gamma[cg + 1] * rsqrtf(var[cg + 1] + BN_EPS);
                float m0 = mean[cg], m1 = mean[cg + 1];
                float t0 = beta[cg], t1 = beta[cg + 1];
                float w00 = w2[cg * 2], w01 = w2[cg * 2 + 1];
                float w10 = w2[(cg + 1) * 2], w11 = w2[(cg + 1) * 2 + 1];
                float z0x = (fmaxf(a[0] + b0, 0.f) - m0) * s0 + t0;
                float z0y = (fmaxf(a[1] + b1, 0.f) - m1) * s1 + t1;
                float z1x = (fmaxf(a[2] + b0, 0.f) - m0) * s0 + t0;
                float z1y = (fmaxf(a[3] + b1, 0.f) - m1) * s1 + t1;
                p0a += z0x * w00 + z0y * w10;
                p0b += z0x * w01 + z0y * w11;
                p1a += z1x * w00 + z1y * w10;
                p1b += z1x * w01 + z1y * w11;
            }
#pragma unroll
            for (int m = 1; m <= 2; m <<= 1) {
                p0a += __shfl_xor_sync(0xffffffffu, p0a, m);
                p0b += __shfl_xor_sync(0xffffffffu, p0b, m);
                p1a += __shfl_xor_sync(0xffffffffu, p1a, m);
                p1b += __shfl_xor_sync(0xffffffffu, p1b, m);
            }
            if ((lane & 3) == 0) {
                int rl0 = mb * 16 + (lane >> 2);
                lpart[rl0][wn][0] = p0a;
                lpart[rl0][wn][1] = p0b;
                lpart[rl0 + 8][wn][0] = p1a;
                lpart[rl0 + 8][wn][1] = p1b;
            }
        }
        __syncthreads();
        if (tid < 64) {
            int gr = brow + tid;
            if (gr < NN) {
                float s0 = 0.f, s1 = 0.f;
#pragma unroll
                for (int w = 0; w < 8; w++) {
                    s0 += lpart[tid][w][0];
                    s1 += lpart[tid][w][1];
                }
                out[gr * 2 + 0] = s0 + b2[0];
                out[gr * 2 + 1] = s1 + b2[1];
            }
        }
    }
}

// ==================== launch ====================
extern "C" void kernel_launch(void* const* d_in, const int* in_sizes, int n_in,
                              void* d_out, int out_size) {
    const float* features = (const float*)d_in[0];
    const int*   eidx     = (const int*)d_in[1];
    const float* ew       = (const float*)d_in[3];   // d_in[2] edgenet_input unused (eval)
    const float* cheb_w   = (const float*)d_in[4];
    const float* w1       = (const float*)d_in[5];
    const float* b1       = (const float*)d_in[6];
    const float* gamma    = (const float*)d_in[7];
    const float* beta     = (const float*)d_in[8];
    const float* mean     = (const float*)d_in[9];
    const float* var      = (const float*)d_in[10];
    const float* w2       = (const float*)d_in[11];
    const float* b2       = (const float*)d_in[12];

    const int* row = eidx;
    const int* col = eidx + NE;
    float* out_logit = (float*)d_out;
    float* out_ew    = (float*)d_out + NN * 2;

    cudaFuncSetAttribute(k_mmagemm<0>, cudaFuncAttributeMaxDynamicSharedMemorySize, GSM_TOTAL);
    cudaFuncSetAttribute(k_mmagemm<1>, cudaFuncAttributeMaxDynamicSharedMemorySize, GSM_TOTAL);

    // fused prep (zero + feature split + weight packs), then graph build
    k_prepall<<<(PREP_TOTAL + 255) / 256, 256>>>(features, cheb_w, w1);
    k_deg<<<(NE + 255) / 256, 256>>>(row, col, ew);
    k_scan<<<1, 1024>>>();
    k_norm<<<(NE + 255) / 256, 256>>>(row, col, ew, out_ew);
    k_scatter<<<(NE + 255) / 256, 256>>>(col);
    k_sortfill<<<(NN + 127) / 128, 128>>>(row);

    int ggrid = (NN + 63) / 64;  // 313
    for (int l = 0; l < LGC; l++) {
        k_prop<<<(NN + 1) / 2, dim3(64, 2)>>>(features, l, 0);
        k_prop<<<(NN + 1) / 2, dim3(64, 2)>>>(features, l, 1);
        k_mmagemm<0><<<ggrid, 256, GSM_TOTAL>>>(l, nullptr, nullptr, nullptr,
                                                nullptr, nullptr, nullptr, nullptr, nullptr);
    }
    k_mmagemm<1><<<ggrid, 256, GSM_TOTAL>>>(3, b1, gamma, beta, mean, var,
                                            w2, b2, out_logit);
}

// round 17
// speedup vs baseline: 1.4601x; 1.4601x over previous
#include <cuda_runtime.h>
#include <cuda_fp16.h>
#include <cstdint>

#define NN 20000
#define NE 320000
#define DD 256
#define LGC 4
#define KCH 768
#define KCL 1024
#define BN_EPS 1e-5f

// ==================== scratch ====================
__device__ float g_deg[NN];
__device__ float g_norm[NE];
__device__ int   g_cnt[NN];
__device__ int   g_cur[NN];
__device__ int   g_ptr[NN + 1];
__device__ int   g_eid[NE];
__device__ int   g_src[NE];
__device__ float g_w[NE];
__device__ float g_t1[(size_t)NN * DD];        // T1 fp32 (prop phase-1 gather input)
__device__ float g_jk[(size_t)NN * 1024];      // JK fp32 (next-layer T0 gather input)
// packed fp16 hi/lo A-operand copies: word w = half2 of cols (2w, 2w+1)
__device__ uint32_t g_fph[(size_t)NN * 128];
__device__ uint32_t g_fpl[(size_t)NN * 128];
__device__ uint32_t g_t1ph[(size_t)NN * 128];
__device__ uint32_t g_t1pl[(size_t)NN * 128];
__device__ uint32_t g_t2ph[(size_t)NN * 128];
__device__ uint32_t g_t2pl[(size_t)NN * 128];
__device__ uint32_t g_jkph[(size_t)NN * 512];
__device__ uint32_t g_jkpl[(size_t)NN * 512];
// transposed fp16 weights (single copy): [256 n][K/2 kpairs]
__device__ uint32_t g_wch[LGC * 256 * (KCH / 2)];
__device__ uint32_t g_wcl[256 * (KCL / 2)];

__device__ __forceinline__ uint32_t packh(__half a, __half b) {
    return (uint32_t)__half_as_ushort(a) | ((uint32_t)__half_as_ushort(b) << 16);
}

// split two fp32 into fp16 hi/lo half2 words (A = hi + lo captures ~22 mantissa bits)
__device__ __forceinline__ void split2(float x, float y, uint32_t& hi, uint32_t& lo) {
    __half h0 = __float2half_rn(x), h1 = __float2half_rn(y);
    float r0 = x - __half2float(h0), r1 = y - __half2float(h1);
    hi = packh(h0, h1);
    lo = packh(__float2half_rn(r0), __float2half_rn(r1));
}

__device__ __forceinline__ uint32_t smem_u32(const void* p) {
    uint32_t a;
    asm("{ .reg .u64 t; cvta.to.shared.u64 t, %1; cvt.u32.u64 %0, t; }" : "=r"(a) : "l"(p));
    return a;
}

__device__ __forceinline__ void ldm_x4(uint32_t r[4], uint32_t addr) {
    asm volatile("ldmatrix.sync.aligned.m8n8.x4.shared.b16 {%0,%1,%2,%3}, [%4];"
                 : "=r"(r[0]), "=r"(r[1]), "=r"(r[2]), "=r"(r[3]) : "r"(addr));
}

__device__ __forceinline__ void mma16816(float c[4], const uint32_t a[4], const uint32_t b0,
                                         const uint32_t b1) {
    asm volatile(
        "mma.sync.aligned.m16n8k16.row.col.f32.f16.f16.f32 "
        "{%0,%1,%2,%3}, {%4,%5,%6,%7}, {%8,%9}, {%0,%1,%2,%3};"
        : "+f"(c[0]), "+f"(c[1]), "+f"(c[2]), "+f"(c[3])
        : "r"(a[0]), "r"(a[1]), "r"(a[2]), "r"(a[3]), "r"(b0), "r"(b1));
}

__device__ __forceinline__ void cpa16(uint32_t dst, const void* src, int sz) {
    asm volatile("cp.async.cg.shared.global [%0], [%1], 16, %2;"
                 :: "r"(dst), "l"(src), "r"(sz));
}
#define CP_COMMIT() asm volatile("cp.async.commit_group;" ::: "memory")
#define CP_WAIT1()  asm volatile("cp.async.wait_group 1;" ::: "memory")
#define CP_WAIT0()  asm volatile("cp.async.wait_group 0;" ::: "memory")

// ==================== setup kernels ====================
// deg (weighted) + cnt (edge count per target) in one pass
__global__ void k_deg(const int* __restrict__ row, const int* __restrict__ col,
                      const float* __restrict__ ew) {
    int e = blockIdx.x * blockDim.x + threadIdx.x;
    if (e < NE) {
        atomicAdd(&g_deg[row[e]], ew[e]);
        atomicAdd(&g_cnt[col[e]], 1);
    }
}

__device__ __forceinline__ float dis_of(float d) {
    float y = 0.f;
    if (d > 0.f) {
        y = rsqrtf(d);
        y = y * (1.5f - 0.5f * d * y * y);  // Newton refine
    }
    return y;
}

__global__ void k_norm(const int* __restrict__ row, const int* __restrict__ col,
                       const float* __restrict__ ew, float* __restrict__ out_ew) {
    int e = blockIdx.x * blockDim.x + threadIdx.x;
    if (e < NE) {
        float w = ew[e];
        float ir = dis_of(g_deg[row[e]]);
        float ic = dis_of(g_deg[col[e]]);
        g_norm[e] = -(ir * w * ic);
        out_ew[e] = w;
    }
}

__global__ void k_scan() {
    __shared__ int sh[1024];
    const int CH = 20;
    int tid = threadIdx.x;
    int base = tid * CH;
    int s = 0;
    for (int i = 0; i < CH; i++) {
        int idx = base + i;
        if (idx < NN) s += g_cnt[idx];
    }
    sh[tid] = s;
    __syncthreads();
    for (int off = 1; off < 1024; off <<= 1) {
        int v = (tid >= off) ? sh[tid - off] : 0;
        __syncthreads();
        sh[tid] += v;
        __syncthreads();
    }
    int run = (tid == 0) ? 0 : sh[tid - 1];
    for (int i = 0; i < CH; i++) {
        int idx = base + i;
        if (idx < NN) { g_ptr[idx] = run; run += g_cnt[idx]; }
    }
    if (tid == 1023) g_ptr[NN] = sh[1023];
}

__global__ void k_scatter(const int* __restrict__ col) {
    int e = blockIdx.x * blockDim.x + threadIdx.x;
    if (e < NE) {
        int c = col[e];
        int pos = g_ptr[c] + atomicAdd(&g_cur[c], 1);
        g_eid[pos] = e;
    }
}

__global__ void k_sortfill(const int* __restrict__ row) {
    int c = blockIdx.x * blockDim.x + threadIdx.x;
    if (c >= NN) return;
    int b = g_ptr[c], t = g_ptr[c + 1];
    for (int i = b + 1; i < t; i++) {
        int v = g_eid[i];
        int j = i - 1;
        while (j >= b && g_eid[j] > v) { g_eid[j + 1] = g_eid[j]; j--; }
        g_eid[j + 1] = v;
    }
    for (int p = b; p < t; p++) {
        int e = g_eid[p];
        g_src[p] = row[e];
        g_w[p] = g_norm[e];
    }
}

// ==================== fused prep: zero + feature split + weight fp16 packs ====================
#define PREP_FEAT_OFF  NN
#define PREP_CHEB_OFF  (NN + NN * 128)
#define PREP_W1_OFF    (PREP_CHEB_OFF + 4 * 98304)
#define PREP_TOTAL     (PREP_W1_OFF + 131072)

__global__ void k_prepall(const float* __restrict__ feat, const float* __restrict__ cheb_w,
                          const float* __restrict__ w1) {
    int idx = blockIdx.x * blockDim.x + threadIdx.x;
    if (idx < NN) {
        g_deg[idx] = 0.f; g_cnt[idx] = 0; g_cur[idx] = 0;
        return;
    }
    if (idx < PREP_CHEB_OFF) {
        int i = idx - PREP_FEAT_OFF;
        int n = i >> 7, w = i & 127;
        float2 v = *(const float2*)(feat + (size_t)n * 256 + 2 * w);
        uint32_t hi, lo;
        split2(v.x, v.y, hi, lo);
        g_fph[i] = hi;
        g_fpl[i] = lo;
        return;
    }
    if (idx < PREP_W1_OFF) {
        int i = idx - PREP_CHEB_OFF;
        int l = i / 98304, o = i % 98304;
        int n = o & 255, kp = o >> 8;             // kp in [0, 384)
        const float* B = cheb_w + (size_t)l * 3 * 256 * 256;
        uint32_t w = packh(__float2half_rn(B[(size_t)(2 * kp) * 256 + n]),
                           __float2half_rn(B[(size_t)(2 * kp + 1) * 256 + n]));
        g_wch[(size_t)l * 256 * (KCH / 2) + (size_t)n * (KCH / 2) + kp] = w;
        return;
    }
    if (idx < PREP_TOTAL) {
        int i = idx - PREP_W1_OFF;
        int n = i & 255, kp = i >> 8;             // kp in [0, 512)
        uint32_t w = packh(__float2half_rn(w1[(size_t)(2 * kp) * 256 + n]),
                           __float2half_rn(w1[(size_t)(2 * kp + 1) * 256 + n]));
        g_wcl[(size_t)n * (KCL / 2) + kp] = w;
    }
}

// ==================== cheb propagation (4-edge unroll — R15 proven config) ====================
__global__ void k_prop(const float* __restrict__ feat, int l, int phase) {
    int c = blockIdx.x * 2 + threadIdx.y;
    if (c >= NN) return;
    int t = threadIdx.x;  // 0..63, float4 each
    const float* xin = (l == 0) ? feat : (g_jk + (size_t)(l - 1) * 256);
    int xstride = (l == 0) ? 256 : 1024;
    const float* xb;
    int xs;
    if (phase == 0) { xb = xin; xs = xstride; }
    else            { xb = g_t1; xs = 256; }

    float4 acc = make_float4(0.f, 0.f, 0.f, 0.f);
    int b = g_ptr[c], e = g_ptr[c + 1];
    int p = b;
    for (; p + 4 <= e; p += 4) {
        float w0 = g_w[p], w1 = g_w[p + 1], w2 = g_w[p + 2], w3 = g_w[p + 3];
        int s0 = g_src[p], s1 = g_src[p + 1], s2 = g_src[p + 2], s3 = g_src[p + 3];
        float4 v0 = *(const float4*)(xb + (size_t)s0 * xs + 4 * t);
        float4 v1 = *(const float4*)(xb + (size_t)s1 * xs + 4 * t);
        float4 v2 = *(const float4*)(xb + (size_t)s2 * xs + 4 * t);
        float4 v3 = *(const float4*)(xb + (size_t)s3 * xs + 4 * t);
        acc.x += w0 * v0.x + w1 * v1.x + w2 * v2.x + w3 * v3.x;
        acc.y += w0 * v0.y + w1 * v1.y + w2 * v2.y + w3 * v3.y;
        acc.z += w0 * v0.z + w1 * v1.z + w2 * v2.z + w3 * v3.z;
        acc.w += w0 * v0.w + w1 * v1.w + w2 * v2.w + w3 * v3.w;
    }
    for (; p < e; p++) {
        float w0 = g_w[p];
        int s0 = g_src[p];
        float4 v0 = *(const float4*)(xb + (size_t)s0 * xs + 4 * t);
        acc.x += w0 * v0.x; acc.y += w0 * v0.y;
        acc.z += w0 * v0.z; acc.w += w0 * v0.w;
    }
    uint32_t h0, l0, h1, l1;
    if (phase == 0) {
        *(float4*)(g_t1 + (size_t)c * 256 + 4 * t) = acc;
        split2(acc.x, acc.y, h0, l0);
        split2(acc.z, acc.w, h1, l1);
        size_t w = (size_t)c * 128 + 2 * t;
        g_t1ph[w] = h0; g_t1ph[w + 1] = h1;
        g_t1pl[w] = l0; g_t1pl[w + 1] = l1;
    } else {
        float4 v0 = *(const float4*)(xin + (size_t)c * xstride + 4 * t);
        acc.x = 2.f * acc.x - v0.x;
        acc.y = 2.f * acc.y - v0.y;
        acc.z = 2.f * acc.z - v0.z;
        acc.w = 2.f * acc.w - v0.w;
        split2(acc.x, acc.y, h0, l0);
        split2(acc.z, acc.w, h1, l1);
        size_t w = (size_t)c * 128 + 2 * t;
        g_t2ph[w] = h0; g_t2ph[w + 1] = h1;
        g_t2pl[w] = l0; g_t2pl[w + 1] = l1;
    }
}

// ==================== mma.sync fp16 GEMM (2-product), BM=64, 2 CTAs/SM ====================
// Grid (313), 256 threads = 8 warps (1 M x 8 N); warp tile 64x32; K-chunk 64.
// SMEM buffer (48KB x2): Ahi 8K | Alo 8K | B 32K, XOR-16B swizzled 128B rows.
// C = (Ah + Al) @ Bh.
#define BUFSZ 49152u
#define GSM_TOTAL (2 * 49152)

template <int EPI>
__global__ void __launch_bounds__(256, 2)
k_mmagemm(int l, const float* __restrict__ bias, const float* __restrict__ gamma,
          const float* __restrict__ beta, const float* __restrict__ mean,
          const float* __restrict__ var, const float* __restrict__ w2,
          const float* __restrict__ b2, float* __restrict__ out) {
    extern __shared__ char smem[];
    __shared__ float lpart[64][8][2];
    const int K = (EPI == 0) ? KCH : KCL;
    const int Khalf = K >> 1;
    const uint32_t* Bw = (EPI == 0) ? (g_wch + (size_t)l * 256 * (KCH / 2)) : g_wcl;
    const int jkoff = l * 256;

    uint32_t sm = smem_u32(smem);
    int tid = threadIdx.x;
    int wid = tid >> 5, lane = tid & 31;
    int wn = wid;                               // 8 warps across N
    int brow = blockIdx.x * 64;

    float acc[4][4][4];
#pragma unroll
    for (int i = 0; i < 4; i++)
#pragma unroll
        for (int j = 0; j < 4; j++)
#pragma unroll
            for (int q = 0; q < 4; q++) acc[i][j][q] = 0.f;

    int a_mi = lane >> 3;
    int a_row = ((a_mi & 1) << 3) + (lane & 7);
    int a_k8 = a_mi >> 1;                       // 16B-chunk offset 0/1
    int b_nrow = (((lane >> 4) & 1) << 3) + (lane & 7);
    int b_k8 = (lane >> 3) & 1;

    const int nchunks = K >> 6;

    auto stage = [&](int c) {
        uint32_t base = sm + (uint32_t)(c & 1) * BUFSZ;
        uint32_t aHi = base, aLo = base + 8192, bS = base + 16384;
        const uint32_t *Ah, *Al;
        int aws, cw;
        if (EPI == 0) {
            int seg = c >> 2, sc = (c & 3) * 32;
            if (seg == 0) {
                if (l == 0) { Ah = g_fph; Al = g_fpl; aws = 128; cw = sc; }
                else { Ah = g_jkph + (size_t)(l - 1) * 128; Al = g_jkpl + (size_t)(l - 1) * 128;
                       aws = 512; cw = sc; }
            } else if (seg == 1) { Ah = g_t1ph; Al = g_t1pl; aws = 128; cw = sc; }
            else                 { Ah = g_t2ph; Al = g_t2pl; aws = 128; cw = sc; }
        } else {
            Ah = g_jkph; Al = g_jkpl; aws = 512; cw = c * 32;
        }
        // A: 64 rows x 8 chunks, hi+lo -> 512 entries, 2/thread (2 cp each)
#pragma unroll
        for (int i = 0; i < 2; i++) {
            int idx = tid + i * 256;            // 0..511
            int r = idx >> 3, ch = idx & 7;
            int gr = brow + r;
            int ok = (gr < NN);
            size_t go = (size_t)(ok ? gr : 0) * aws + cw + ch * 4;
            uint32_t d = (uint32_t)(r * 128) + ((uint32_t)(ch ^ (r & 7)) << 4);
            cpa16(aHi + d, Ah + go, ok ? 16 : 0);
            cpa16(aLo + d, Al + go, ok ? 16 : 0);
        }
        // B: 256 rows x 8 chunks = 2048 -> 8/thread
#pragma unroll
        for (int i = 0; i < 8; i++) {
            int idx = tid + i * 256;            // 0..2047
            int n = idx >> 3, ch = idx & 7;
            size_t go = (size_t)n * Khalf + c * 32 + ch * 4;
            uint32_t d = (uint32_t)(n * 128) + ((uint32_t)(ch ^ (n & 7)) << 4);
            cpa16(bS + d, Bw + go, 16);
        }
        CP_COMMIT();
    };

    stage(0);
    for (int c = 0; c < nchunks; c++) {
        if (c + 1 < nchunks) { stage(c + 1); CP_WAIT1(); }
        else                 { CP_WAIT0(); }
        __syncthreads();

        uint32_t base = sm + (uint32_t)(c & 1) * BUFSZ;
        uint32_t aHi = base, aLo = base + 8192, bS = base + 16384;
#pragma unroll
        for (int kb = 0; kb < 4; kb++) {
            uint32_t bh[2][4];
#pragma unroll
            for (int np = 0; np < 2; np++) {
                int row = wn * 32 + np * 16 + b_nrow;
                uint32_t off = (uint32_t)(row * 128)
                             + ((uint32_t)((kb * 2 + b_k8) ^ (row & 7)) << 4);
                ldm_x4(bh[np], bS + off);
            }
#pragma unroll
            for (int mb = 0; mb < 4; mb++) {
                uint32_t ah[4], al[4];
                int row = mb * 16 + a_row;
                uint32_t off = (uint32_t)(row * 128)
                             + ((uint32_t)((kb * 2 + a_k8) ^ (row & 7)) << 4);
                ldm_x4(ah, aHi + off);
                ldm_x4(al, aLo + off);
#pragma unroll
                for (int nb = 0; nb < 4; nb++) {
                    int p = nb >> 1, q = (nb & 1) * 2;
                    mma16816(acc[mb][nb], ah, bh[p][q], bh[p][q + 1]);
                    mma16816(acc[mb][nb], al, bh[p][q], bh[p][q + 1]);
                }
            }
        }
        __syncthreads();
    }

    int gr_base = brow + (lane >> 2);
    int cg_base = wn * 32 + (lane & 3) * 2;
    if (EPI == 0) {
#pragma unroll
        for (int mb = 0; mb < 4; mb++) {
#pragma unroll
            for (int nb = 0; nb < 4; nb++) {
                int cg = cg_base + nb * 8;
                int r0 = gr_base + mb * 16;
                int r1 = r0 + 8;
                float* a = acc[mb][nb];
                if (r0 < NN) {
                    float vx = fmaxf(a[0], 0.f), vy = fmaxf(a[1], 0.f);
                    *(float2*)(g_jk + (size_t)r0 * 1024 + jkoff + cg) = make_float2(vx, vy);
                    uint32_t hi, lo;
                    split2(vx, vy, hi, lo);
                    size_t w = (size_t)r0 * 512 + ((jkoff + cg) >> 1);
                    g_jkph[w] = hi;
                    g_jkpl[w] = lo;
                }
                if (r1 < NN) {
                    float vx = fmaxf(a[2], 0.f), vy = fmaxf(a[3], 0.f);
                    *(float2*)(g_jk + (size_t)r1 * 1024 + jkoff + cg) = make_float2(vx, vy);
                    uint32_t hi, lo;
                    split2(vx, vy, hi, lo);
                    size_t w = (size_t)r1 * 512 + ((jkoff + cg) >> 1);
                    g_jkph[w] = hi;
                    g_jkpl[w] = lo;
                }
            }
        }
    } else {
#pragma unroll
        for (int mb = 0; mb < 4; mb++) {
            float p0a = 0.f, p0b = 0.f, p1a = 0.f, p1b = 0.f;
#pragma unroll
            for (int nb = 0; nb < 4; nb++) {
                int cg = cg_base + nb * 8;
                float* a = acc[mb][nb];
                float b0 = bias[cg], b1 = bias[cg + 1];
                float s0 = gamma[cg] * rsqrtf(var[cg] + BN_EPS);
                float s1 = gamma[cg + 1] * rsqrtf(var[cg + 1] + BN_EPS);
                float m0 = mean[cg], m1 = mean[cg + 1];
                float t0 = beta[cg], t1 = beta[cg + 1];
                float w00 = w2[cg * 2], w01 = w2[cg * 2 + 1];
                float w10 = w2[(cg + 1) * 2], w11 = w2[(cg + 1) * 2 + 1];
                float z0x = (fmaxf(a[0] + b0, 0.f) - m0) * s0 + t0;
                float z0y = (fmaxf(a[1] + b1, 0.f) - m1) * s1 + t1;
                float z1x = (fmaxf(a[2] + b0, 0.f) - m0) * s0 + t0;
                float z1y = (fmaxf(a[3] + b1, 0.f) - m1) * s1 + t1;
                p0a += z0x * w00 + z0y * w10;
                p0b += z0x * w01 + z0y * w11;
                p1a += z1x * w00 + z1y * w10;
                p1b += z1x * w01 + z1y * w11;
            }
#pragma unroll
            for (int m = 1; m <= 2; m <<= 1) {
                p0a += __shfl_xor_sync(0xffffffffu, p0a, m);
                p0b += __shfl_xor_sync(0xffffffffu, p0b, m);
                p1a += __shfl_xor_sync(0xffffffffu, p1a, m);
                p1b += __shfl_xor_sync(0xffffffffu, p1b, m);
            }
            if ((lane & 3) == 0) {
                int rl0 = mb * 16 + (lane >> 2);
                lpart[rl0][wn][0] = p0a;
                lpart[rl0][wn][1] = p0b;
                lpart[rl0 + 8][wn][0] = p1a;
                lpart[rl0 + 8][wn][1] = p1b;
            }
        }
        __syncthreads();
        if (tid < 64) {
            int gr = brow + tid;
            if (gr < NN) {
                float s0 = 0.f, s1 = 0.f;
#pragma unroll
                for (int w = 0; w < 8; w++) {
                    s0 += lpart[tid][w][0];
                    s1 += lpart[tid][w][1];
                }
                out[gr * 2 + 0] = s0 + b2[0];
                out[gr * 2 + 1] = s1 + b2[1];
            }
        }
    }
}

// ==================== launch ====================
extern "C" void kernel_launch(void* const* d_in, const int* in_sizes, int n_in,
                              void* d_out, int out_size) {
    const float* features = (const float*)d_in[0];
    const int*   eidx     = (const int*)d_in[1];
    const float* ew       = (const float*)d_in[3];   // d_in[2] edgenet_input unused (eval)
    const float* cheb_w   = (const float*)d_in[4];
    const float* w1       = (const float*)d_in[5];
    const float* b1       = (const float*)d_in[6];
    const float* gamma    = (const float*)d_in[7];
    const float* beta     = (const float*)d_in[8];
    const float* mean     = (const float*)d_in[9];
    const float* var      = (const float*)d_in[10];
    const float* w2       = (const float*)d_in[11];
    const float* b2       = (const float*)d_in[12];

    const int* row = eidx;
    const int* col = eidx + NE;
    float* out_logit = (float*)d_out;
    float* out_ew    = (float*)d_out + NN * 2;

    cudaFuncSetAttribute(k_mmagemm<0>, cudaFuncAttributeMaxDynamicSharedMemorySize, GSM_TOTAL);
    cudaFuncSetAttribute(k_mmagemm<1>, cudaFuncAttributeMaxDynamicSharedMemorySize, GSM_TOTAL);

    // fused prep (zero + feature split + weight packs), then graph build
    k_prepall<<<(PREP_TOTAL + 255) / 256, 256>>>(features, cheb_w, w1);
    k_deg<<<(NE + 255) / 256, 256>>>(row, col, ew);
    k_scan<<<1, 1024>>>();
    k_norm<<<(NE + 255) / 256, 256>>>(row, col, ew, out_ew);
    k_scatter<<<(NE + 255) / 256, 256>>>(col);
    k_sortfill<<<(NN + 127) / 128, 128>>>(row);

    int ggrid = (NN + 63) / 64;  // 313
    for (int l = 0; l < LGC; l++) {
        k_prop<<<(NN + 1) / 2, dim3(64, 2)>>>(features, l, 0);
        k_prop<<<(NN + 1) / 2, dim3(64, 2)>>>(features, l, 1);
        k_mmagemm<0><<<ggrid, 256, GSM_TOTAL>>>(l, nullptr, nullptr, nullptr,
                                                nullptr, nullptr, nullptr, nullptr, nullptr);
    }
    k_mmagemm<1><<<ggrid, 256, GSM_TOTAL>>>(3, b1, gamma, beta, mean, var,
                                            w2, b2, out_logit);
}